// round 2
// baseline (speedup 1.0000x reference)
#include <cuda_runtime.h>
#include <cuda_bf16.h>
#include <math.h>

// ---------------------------------------------------------------------------
// ConvKAN layer:
//   patches P[N,576] from x (3x3 SAME, patch idx i = c*9 + kh*3 + kw)
//   out = silu(P) @ base_w^T + einsum('nig,oig', Bspline(P), spline_w) + bias
// Reformulated:
//   A[n,h,w, c*7+t] : t=0 -> silu(x), t=1..6 -> 6 uniform cubic B-spline bases
//   out = conv3x3(A, Wp) + bias,  K = 9*448 = 4032
// NOTE: SAME padding pads x with zeros, and the reference evaluates the
// splines on those zeros -> halo entries must hold features(v=0), which are
// NOT all zero (bases(0) = {0, 1/48, 23/48, 23/48, 1/48, 0}).
// ---------------------------------------------------------------------------

#define B_      8
#define H_      64
#define W_      64
#define CIN     64
#define COUT    128
#define FEAT    7            // silu + 6 bases
#define CEXP    (CIN*FEAT)   // 448
#define HP      (H_+2)       // 66 padded
#define WP      (W_+2)
#define KTOT    (9*CEXP)     // 4032

// scratch (static device globals: allocation-free)
__device__ float g_A[(size_t)B_*HP*WP*CEXP];   // ~62 MB, halo = features(0)
__device__ float g_Wp[(size_t)KTOT*COUT];      // packed weights, [k][o]

// ---------------------------------------------------------------------------
// Kernel 1: expand x -> A (silu + B-spline bases) INCLUDING halo with v=0.
// Knots: t_i = -3 + i*(2/3), i=0..9. Cubic uniform B-spline closed form:
// interval j = floor((x+3)*1.5) in [0,8], u = frac:
//   pieces {(1-u)^3, 3u^3-6u^2+4, -3u^3+3u^2+3u+1, u^3}/6 -> bases j-3..j
// outside [-3,3): all bases zero (matches half-open order-0 indicators).
// ---------------------------------------------------------------------------
__global__ void expand_kernel(const float* __restrict__ x) {
    int idx = blockIdx.x * blockDim.x + threadIdx.x;  // (pixel, channel)
    if (idx >= B_*HP*WP*CIN) return;
    int c   = idx & (CIN-1);
    int pix = idx >> 6;
    int wp  = pix % WP;
    int t1  = pix / WP;
    int hp  = t1 % HP;
    int n   = t1 / HP;

    float* dst = g_A + (size_t)pix * CEXP + c * FEAT;

    bool halo = (hp == 0 || hp == HP-1 || wp == 0 || wp == WP-1);
    float v = halo ? 0.0f
                   : x[(((size_t)n * H_ + (hp-1)) * W_ + (wp-1)) * CIN + c];

    // silu
    float s = v / (1.0f + expf(-v));

    // uniform cubic B-spline bases
    float b0=0.f,b1=0.f,b2=0.f,b3=0.f,b4=0.f,b5=0.f;
    float tpos = (v + 3.0f) * 1.5f;
    float fj = floorf(tpos);
    int j = (int)fj;
    if (j >= 0 && j <= 8) {
        float u  = tpos - fj;
        float um = 1.0f - u;
        float u2 = u*u, u3 = u2*u;
        const float k6 = 1.0f/6.0f;
        float n0 = um*um*um*k6;
        float n1 = (3.0f*u3 - 6.0f*u2 + 4.0f)*k6;
        float n2 = (-3.0f*u3 + 3.0f*u2 + 3.0f*u + 1.0f)*k6;
        float n3 = u3*k6;
        int m;
        m = j-3; if (m==0) b0=n0; else if (m==1) b1=n0; else if (m==2) b2=n0; else if (m==3) b3=n0; else if (m==4) b4=n0; else if (m==5) b5=n0;
        m = j-2; if (m==0) b0=n1; else if (m==1) b1=n1; else if (m==2) b2=n1; else if (m==3) b3=n1; else if (m==4) b4=n1; else if (m==5) b5=n1;
        m = j-1; if (m==0) b0=n2; else if (m==1) b1=n2; else if (m==2) b2=n2; else if (m==3) b3=n2; else if (m==4) b4=n2; else if (m==5) b5=n2;
        m = j;   if (m==0) b0=n3; else if (m==1) b1=n3; else if (m==2) b2=n3; else if (m==3) b3=n3; else if (m==4) b4=n3; else if (m==5) b5=n3;
    }
    dst[0]=s; dst[1]=b0; dst[2]=b1; dst[3]=b2; dst[4]=b3; dst[5]=b4; dst[6]=b5;
}

// ---------------------------------------------------------------------------
// Kernel 2: pack weights into g_Wp[k][o],
// k = tap*448 + c*7 + t, tap = kh*3+kw; patch index i = c*9 + tap.
// ---------------------------------------------------------------------------
__global__ void wpack_kernel(const float* __restrict__ base_w,
                             const float* __restrict__ spline_w) {
    int idx = blockIdx.x * blockDim.x + threadIdx.x;  // KTOT*COUT
    if (idx >= KTOT*COUT) return;
    int o = idx & (COUT-1);
    int k = idx >> 7;
    int tap = k / CEXP;
    int cc  = k % CEXP;
    int c   = cc / FEAT;
    int t   = cc % FEAT;
    int i   = c * 9 + tap;
    float w = (t == 0) ? base_w[(size_t)o * 576 + i]
                       : spline_w[((size_t)o * 576 + i) * 6 + (t - 1)];
    g_Wp[(size_t)k * COUT + o] = w;
}

// ---------------------------------------------------------------------------
// Kernel 3: conv-as-GEMM. One block = one (n,h) row: 64 pixels x 128 outputs.
// K loop = 9 taps x 448 channels, BK=16. 256 threads, micro-tile 8(m) x 4(n).
// ---------------------------------------------------------------------------
#define BK 16
#define AS_STRIDE 68   // pad: conflict-free transposed stores, keeps 16B align

__global__ __launch_bounds__(256) void convkan_gemm(
        const float* __restrict__ bias, float* __restrict__ out) {
    __shared__ __align__(16) float As[BK][AS_STRIDE];  // [k][pixel]
    __shared__ __align__(16) float Ws[BK][COUT];       // [k][out]

    int r = blockIdx.x;            // 0..511 = n*64 + h
    int n = r >> 6;
    int h = r & 63;
    int tid = threadIdx.x;
    int tm = tid >> 5;             // 0..7  -> pixels tm*8..tm*8+7
    int tn = tid & 31;             // 0..31 -> outputs tn*4..tn*4+3

    float acc[8][4];
    #pragma unroll
    for (int i = 0; i < 8; i++)
        #pragma unroll
        for (int j = 0; j < 4; j++) acc[i][j] = 0.0f;

    const int p_ld = tid >> 2;          // 0..63 pixel for A tile load
    const int c4   = (tid & 3) * 4;     // 0,4,8,12

    for (int tap = 0; tap < 9; ++tap) {
        int kh = tap / 3, kw = tap % 3;
        const float* Arow = g_A + (((size_t)n * HP + (h + kh)) * WP + kw) * CEXP;
        const float* Wtap = g_Wp + (size_t)tap * CEXP * COUT;

        for (int cc0 = 0; cc0 < CEXP; cc0 += BK) {
            // global loads first (overlap latency with address math)
            float4 va = *(const float4*)(Arow + (size_t)p_ld * CEXP + cc0 + c4);
            int idx1 = tid + 256;
            float4 w0 = *(const float4*)(Wtap + ((size_t)(cc0 + (tid  >> 5))) * COUT + (tid  & 31) * 4);
            float4 w1 = *(const float4*)(Wtap + ((size_t)(cc0 + (idx1 >> 5))) * COUT + (idx1 & 31) * 4);

            // transposed A store (stride 68 -> conflict-free)
            As[c4+0][p_ld] = va.x;
            As[c4+1][p_ld] = va.y;
            As[c4+2][p_ld] = va.z;
            As[c4+3][p_ld] = va.w;
            *(float4*)&Ws[tid  >> 5][(tid  & 31) * 4] = w0;
            *(float4*)&Ws[idx1 >> 5][(idx1 & 31) * 4] = w1;
            __syncthreads();

            #pragma unroll
            for (int kk = 0; kk < BK; ++kk) {
                float4 a0 = *(const float4*)&As[kk][tm*8];
                float4 a1 = *(const float4*)&As[kk][tm*8+4];
                float4 bv = *(const float4*)&Ws[kk][tn*4];
                float av[8] = {a0.x,a0.y,a0.z,a0.w,a1.x,a1.y,a1.z,a1.w};
                float bb[4] = {bv.x,bv.y,bv.z,bv.w};
                #pragma unroll
                for (int mi = 0; mi < 8; mi++)
                    #pragma unroll
                    for (int nj = 0; nj < 4; nj++)
                        acc[mi][nj] = fmaf(av[mi], bb[nj], acc[mi][nj]);
            }
            __syncthreads();
        }
    }

    float4 bv4 = *(const float4*)(bias + tn * 4);
    #pragma unroll
    for (int mi = 0; mi < 8; mi++) {
        int w = tm * 8 + mi;
        float4 o4;
        o4.x = acc[mi][0] + bv4.x;
        o4.y = acc[mi][1] + bv4.y;
        o4.z = acc[mi][2] + bv4.z;
        o4.w = acc[mi][3] + bv4.w;
        *(float4*)(out + (((size_t)r * W_ + w) * COUT) + tn * 4) = o4;
    }
}

// ---------------------------------------------------------------------------
extern "C" void kernel_launch(void* const* d_in, const int* in_sizes, int n_in,
                              void* d_out, int out_size) {
    const float* x        = (const float*)d_in[0];
    const float* base_w   = (const float*)d_in[1];
    const float* spline_w = (const float*)d_in[2];
    const float* bias     = (const float*)d_in[3];
    float* out = (float*)d_out;

    {
        int total = B_*HP*WP*CIN;
        expand_kernel<<<(total + 255)/256, 256>>>(x);
    }
    {
        int total = KTOT*COUT;
        wpack_kernel<<<(total + 255)/256, 256>>>(base_w, spline_w);
    }
    convkan_gemm<<<B_*H_, 256>>>(bias, out);
}

// round 3
// speedup vs baseline: 2.0091x; 2.0091x over previous
#include <cuda_runtime.h>
#include <cuda_bf16.h>
#include <math.h>
#include <stdint.h>

// ---------------------------------------------------------------------------
// ConvKAN layer as conv3x3 GEMM over expanded features (silu + 6 cubic
// B-spline bases per input element).  out = A(expanded) * Wp + bias.
//   M = 8*64*64 = 32768 pixels, N = 128, K = 9*448 = 4032.
// GEMM runs on tensor cores: mma.sync.m16n8k8 TF32 (inputs pre-rounded RNA).
// ---------------------------------------------------------------------------

#define B_      8
#define H_      64
#define W_      64
#define CIN     64
#define COUT    128
#define FEAT    7
#define CEXP    (CIN*FEAT)   // 448
#define HP      (H_+2)
#define WP      (W_+2)
#define KTOT    (9*CEXP)     // 4032

__device__ float g_A[(size_t)B_*HP*WP*CEXP];   // tf32-rounded, halo=features(0)
__device__ float g_Wp[(size_t)KTOT*COUT];      // tf32-rounded packed weights [k][o]

__device__ __forceinline__ float tf32r(float x) {
    uint32_t u;
    asm("cvt.rna.tf32.f32 %0, %1;" : "=r"(u) : "f"(x));
    return __uint_as_float(u);
}

// ---------------------------------------------------------------------------
// Kernel 1: expand x -> A (incl. halo = features(0); bases(0) != 0!)
// ---------------------------------------------------------------------------
__global__ void expand_kernel(const float* __restrict__ x) {
    int idx = blockIdx.x * blockDim.x + threadIdx.x;
    if (idx >= B_*HP*WP*CIN) return;
    int c   = idx & (CIN-1);
    int pix = idx >> 6;
    int wp  = pix % WP;
    int t1  = pix / WP;
    int hp  = t1 % HP;
    int n   = t1 / HP;

    float* dst = g_A + (size_t)pix * CEXP + c * FEAT;

    bool halo = (hp == 0 || hp == HP-1 || wp == 0 || wp == WP-1);
    float v = halo ? 0.0f
                   : x[(((size_t)n * H_ + (hp-1)) * W_ + (wp-1)) * CIN + c];

    float s = v / (1.0f + expf(-v));

    float b0=0.f,b1=0.f,b2=0.f,b3=0.f,b4=0.f,b5=0.f;
    float tpos = (v + 3.0f) * 1.5f;
    float fj = floorf(tpos);
    int j = (int)fj;
    if (j >= 0 && j <= 8) {
        float u  = tpos - fj;
        float um = 1.0f - u;
        float u2 = u*u, u3 = u2*u;
        const float k6 = 1.0f/6.0f;
        float n0 = um*um*um*k6;
        float n1 = (3.0f*u3 - 6.0f*u2 + 4.0f)*k6;
        float n2 = (-3.0f*u3 + 3.0f*u2 + 3.0f*u + 1.0f)*k6;
        float n3 = u3*k6;
        int m;
        m = j-3; if (m==0) b0=n0; else if (m==1) b1=n0; else if (m==2) b2=n0; else if (m==3) b3=n0; else if (m==4) b4=n0; else if (m==5) b5=n0;
        m = j-2; if (m==0) b0=n1; else if (m==1) b1=n1; else if (m==2) b2=n1; else if (m==3) b3=n1; else if (m==4) b4=n1; else if (m==5) b5=n1;
        m = j-1; if (m==0) b0=n2; else if (m==1) b1=n2; else if (m==2) b2=n2; else if (m==3) b3=n2; else if (m==4) b4=n2; else if (m==5) b5=n2;
        m = j;   if (m==0) b0=n3; else if (m==1) b1=n3; else if (m==2) b2=n3; else if (m==3) b3=n3; else if (m==4) b4=n3; else if (m==5) b5=n3;
    }
    dst[0]=tf32r(s);  dst[1]=tf32r(b0); dst[2]=tf32r(b1); dst[3]=tf32r(b2);
    dst[4]=tf32r(b3); dst[5]=tf32r(b4); dst[6]=tf32r(b5);
}

// ---------------------------------------------------------------------------
// Kernel 2: pack weights g_Wp[k][o], k = tap*448 + c*7 + t, i = c*9 + tap
// ---------------------------------------------------------------------------
__global__ void wpack_kernel(const float* __restrict__ base_w,
                             const float* __restrict__ spline_w) {
    int idx = blockIdx.x * blockDim.x + threadIdx.x;
    if (idx >= KTOT*COUT) return;
    int o = idx & (COUT-1);
    int k = idx >> 7;
    int tap = k / CEXP;
    int cc  = k % CEXP;
    int c   = cc / FEAT;
    int t   = cc % FEAT;
    int i   = c * 9 + tap;
    float w = (t == 0) ? base_w[(size_t)o * 576 + i]
                       : spline_w[((size_t)o * 576 + i) * 6 + (t - 1)];
    g_Wp[(size_t)k * COUT + o] = tf32r(w);
}

// ---------------------------------------------------------------------------
// Kernel 3: TF32 tensor-core GEMM.
// Block: BM=128 pixels (2 image rows) x BN=128 outputs, BK=16.
// 8 warps = 4(m) x 2(n); warp tile 32x64 = 2x8 m16n8k8 mma tiles.
// Single-buffer smem + register prefetch pipeline.
// As stride 20, Bs stride 132 -> conflict-free fragment loads.
// ---------------------------------------------------------------------------
#define BK 16
#define AS_ST 20
#define BS_ST 132
#define NKT (KTOT/BK)      // 252
#define CT_PER_TAP (CEXP/BK)  // 28

__global__ __launch_bounds__(256, 2) void convkan_mma(
        const float* __restrict__ bias, float* __restrict__ out) {
    __shared__ __align__(16) float As[128][AS_ST];
    __shared__ __align__(16) float Bs[BK][BS_ST];

    const int bid  = blockIdx.x;          // 0..255
    const int n    = bid >> 5;
    const int h0   = (bid & 31) << 1;     // 2 image rows
    const int tid  = threadIdx.x;
    const int warp = tid >> 5;
    const int lane = tid & 31;
    const int gid  = lane >> 2;
    const int tig  = lane & 3;
    const int wm   = (warp & 3) * 32;
    const int wn   = (warp >> 2) * 64;

    // A loader: pixel p_ld, half of 16 channels
    const int p_ld = tid >> 1;            // 0..127
    const int ahalf = (tid & 1) * 8;
    const int h_l  = p_ld >> 6;
    const int w_l  = p_ld & 63;
    // B loader: row (k within tile), float4 pair
    const int brow = tid >> 4;            // 0..15
    const int bf4  = (tid & 15) * 2;      // float4 index base

    float acc[2][8][4];
    #pragma unroll
    for (int mt = 0; mt < 2; mt++)
        #pragma unroll
        for (int nt = 0; nt < 8; nt++)
            #pragma unroll
            for (int q = 0; q < 4; q++) acc[mt][nt][q] = 0.0f;

    float4 pa[2], pb[2];

    // prefetch tile 0 (tap 0, ct 0 -> kh=0, kw=0)
    {
        const float* ap = g_A + (((size_t)(n*HP + h0 + h_l)) * WP + w_l) * CEXP + ahalf;
        pa[0] = *(const float4*)(ap);
        pa[1] = *(const float4*)(ap + 4);
        const float* bp = g_Wp + (size_t)brow * COUT + bf4 * 4;
        pb[0] = *(const float4*)(bp);
        pb[1] = *(const float4*)(bp + 4);
    }

    for (int kt = 0; kt < NKT; ++kt) {
        // store prefetched tile
        *(float4*)&As[p_ld][ahalf]     = pa[0];
        *(float4*)&As[p_ld][ahalf + 4] = pa[1];
        *(float4*)&Bs[brow][bf4 * 4]     = pb[0];
        *(float4*)&Bs[brow][bf4 * 4 + 4] = pb[1];
        __syncthreads();

        // prefetch next tile
        if (kt + 1 < NKT) {
            int knext = kt + 1;
            int tap = knext / CT_PER_TAP;
            int ct  = knext % CT_PER_TAP;
            int kh  = tap / 3, kw = tap - kh * 3;
            const float* ap = g_A
                + (((size_t)(n*HP + h0 + h_l + kh)) * WP + (w_l + kw)) * CEXP
                + ct * BK + ahalf;
            pa[0] = *(const float4*)(ap);
            pa[1] = *(const float4*)(ap + 4);
            const float* bp = g_Wp
                + ((size_t)tap * CEXP + ct * BK + brow) * COUT + bf4 * 4;
            pb[0] = *(const float4*)(bp);
            pb[1] = *(const float4*)(bp + 4);
        }

        // compute: 2 k-steps of m16n8k8
        #pragma unroll
        for (int kk = 0; kk < 2; ++kk) {
            const int kb = kk * 8;
            uint32_t afr[2][4];
            #pragma unroll
            for (int mt = 0; mt < 2; mt++) {
                int r0 = wm + mt * 16 + gid;
                afr[mt][0] = __float_as_uint(As[r0    ][kb + tig    ]);
                afr[mt][1] = __float_as_uint(As[r0 + 8][kb + tig    ]);
                afr[mt][2] = __float_as_uint(As[r0    ][kb + tig + 4]);
                afr[mt][3] = __float_as_uint(As[r0 + 8][kb + tig + 4]);
            }
            uint32_t bfr[8][2];
            #pragma unroll
            for (int nt = 0; nt < 8; nt++) {
                int cn = wn + nt * 8 + gid;
                bfr[nt][0] = __float_as_uint(Bs[kb + tig    ][cn]);
                bfr[nt][1] = __float_as_uint(Bs[kb + tig + 4][cn]);
            }
            #pragma unroll
            for (int mt = 0; mt < 2; mt++)
                #pragma unroll
                for (int nt = 0; nt < 8; nt++) {
                    float* d = acc[mt][nt];
                    asm volatile(
                        "mma.sync.aligned.m16n8k8.row.col.f32.tf32.tf32.f32 "
                        "{%0,%1,%2,%3}, {%4,%5,%6,%7}, {%8,%9}, {%0,%1,%2,%3};\n"
                        : "+f"(d[0]), "+f"(d[1]), "+f"(d[2]), "+f"(d[3])
                        : "r"(afr[mt][0]), "r"(afr[mt][1]),
                          "r"(afr[mt][2]), "r"(afr[mt][3]),
                          "r"(bfr[nt][0]), "r"(bfr[nt][1]));
                }
        }
        __syncthreads();
    }

    // epilogue
    #pragma unroll
    for (int nt = 0; nt < 8; nt++) {
        int col = wn + nt * 8 + tig * 2;
        float bx = bias[col], by = bias[col + 1];
        #pragma unroll
        for (int mt = 0; mt < 2; mt++) {
            int row0 = bid * 128 + wm + mt * 16 + gid;
            float2 v0 = make_float2(acc[mt][nt][0] + bx, acc[mt][nt][1] + by);
            float2 v1 = make_float2(acc[mt][nt][2] + bx, acc[mt][nt][3] + by);
            *(float2*)(out + (size_t)row0 * COUT + col)       = v0;
            *(float2*)(out + (size_t)(row0 + 8) * COUT + col) = v1;
        }
    }
}

// ---------------------------------------------------------------------------
extern "C" void kernel_launch(void* const* d_in, const int* in_sizes, int n_in,
                              void* d_out, int out_size) {
    const float* x        = (const float*)d_in[0];
    const float* base_w   = (const float*)d_in[1];
    const float* spline_w = (const float*)d_in[2];
    const float* bias     = (const float*)d_in[3];
    float* out = (float*)d_out;

    {
        int total = B_*HP*WP*CIN;
        expand_kernel<<<(total + 255)/256, 256>>>(x);
    }
    {
        int total = KTOT*COUT;
        wpack_kernel<<<(total + 255)/256, 256>>>(base_w, spline_w);
    }
    convkan_mma<<<256, 256>>>(bias, out);
}

// round 5
// speedup vs baseline: 4.2527x; 2.1166x over previous
#include <cuda_runtime.h>
#include <cuda_fp16.h>
#include <math.h>
#include <stdint.h>

// ---------------------------------------------------------------------------
// ConvKAN as conv3x3-GEMM over expanded features (silu + 6 cubic B-spline
// bases), fp16 inputs (same 10 mantissa bits as tf32), fp32 accumulation.
//   M = 32768 pixels, N = 128 outputs, K = 9*448 = 4032
// GEMM: mma.sync.m16n8k16.f32.f16.f16.f32, double-buffered smem,
// conflict-free vectorized fragment loads, 1 barrier per K-tile.
// ---------------------------------------------------------------------------

#define B_      8
#define H_      64
#define W_      64
#define CIN     64
#define COUT    128
#define FEAT    7
#define CEXP    (CIN*FEAT)   // 448
#define HP      (H_+2)
#define WP      (W_+2)
#define KTOT    (9*CEXP)     // 4032
#define BKH     32           // halves per K-tile
#define NCH     (CEXP/BKH)   // 14 chunks per tap
#define NIT     (9*NCH)      // 126 K-tiles

__device__ __align__(128) __half g_A[(size_t)B_*HP*WP*CEXP];  // expanded (halo=f(0))
__device__ __align__(128) __half g_Wt[(size_t)COUT*KTOT];     // packed weights [o][k]

// ---------------------------------------------------------------------------
// Kernel 1: expand x -> A (incl. halo = features(0); bases(0) != 0!)
// ---------------------------------------------------------------------------
__global__ void expand_kernel(const float* __restrict__ x) {
    int idx = blockIdx.x * blockDim.x + threadIdx.x;
    if (idx >= B_*HP*WP*CIN) return;
    int c   = idx & (CIN-1);
    int pix = idx >> 6;
    int wp  = pix % WP;
    int t1  = pix / WP;
    int hp  = t1 % HP;
    int n   = t1 / HP;

    __half* dst = g_A + (size_t)pix * CEXP + c * FEAT;
    bool halo = (hp == 0 || hp == HP-1 || wp == 0 || wp == WP-1);
    float v = halo ? 0.0f
                   : x[(((size_t)n * H_ + (hp-1)) * W_ + (wp-1)) * CIN + c];

    float s = v / (1.0f + expf(-v));

    float b0=0.f,b1=0.f,b2=0.f,b3=0.f,b4=0.f,b5=0.f;
    float tpos = (v + 3.0f) * 1.5f;
    float fj = floorf(tpos);
    int j = (int)fj;
    if (j >= 0 && j <= 8) {
        float u  = tpos - fj;
        float um = 1.0f - u;
        float u2 = u*u, u3 = u2*u;
        const float k6 = 1.0f/6.0f;
        float n0 = um*um*um*k6;
        float n1 = (3.0f*u3 - 6.0f*u2 + 4.0f)*k6;
        float n2 = (-3.0f*u3 + 3.0f*u2 + 3.0f*u + 1.0f)*k6;
        float n3 = u3*k6;
        int m;
        m = j-3; if (m==0) b0=n0; else if (m==1) b1=n0; else if (m==2) b2=n0; else if (m==3) b3=n0; else if (m==4) b4=n0; else if (m==5) b5=n0;
        m = j-2; if (m==0) b0=n1; else if (m==1) b1=n1; else if (m==2) b2=n1; else if (m==3) b3=n1; else if (m==4) b4=n1; else if (m==5) b5=n1;
        m = j-1; if (m==0) b0=n2; else if (m==1) b1=n2; else if (m==2) b2=n2; else if (m==3) b3=n2; else if (m==4) b4=n2; else if (m==5) b5=n2;
        m = j;   if (m==0) b0=n3; else if (m==1) b1=n3; else if (m==2) b2=n3; else if (m==3) b3=n3; else if (m==4) b4=n3; else if (m==5) b5=n3;
    }
    dst[0]=__float2half_rn(s);  dst[1]=__float2half_rn(b0);
    dst[2]=__float2half_rn(b1); dst[3]=__float2half_rn(b2);
    dst[4]=__float2half_rn(b3); dst[5]=__float2half_rn(b4);
    dst[6]=__float2half_rn(b5);
}

// ---------------------------------------------------------------------------
// Kernel 2: pack weights -> g_Wt[o][k], k = tap*448 + c*7 + t, i = c*9 + tap
// ---------------------------------------------------------------------------
__global__ void wpack_kernel(const float* __restrict__ base_w,
                             const float* __restrict__ spline_w) {
    int idx = blockIdx.x * blockDim.x + threadIdx.x;
    if (idx >= COUT*KTOT) return;
    int o = idx / KTOT;
    int k = idx - o * KTOT;
    int tap = k / CEXP;
    int cc  = k - tap * CEXP;
    int c   = cc / FEAT;
    int t   = cc - c * FEAT;
    int i   = c * 9 + tap;
    float w = (t == 0) ? base_w[(size_t)o * 576 + i]
                       : spline_w[((size_t)o * 576 + i) * 6 + (t - 1)];
    g_Wt[idx] = __float2half_rn(w);
}

// ---------------------------------------------------------------------------
// Kernel 3: fp16 tensor-core GEMM.
// Block: BM=128 pixels (2 image rows) x BN=128 outputs, K-tile = 32 halves.
// 8 warps = 4(m) x 2(n); warp tile 32x64 = 2x8 m16n8k16 tiles per k-step.
// Double-buffered smem, row stride 40 halves (80B): fragment LDS.32 at
// addr/4 = 20*gid + tig (mod 32) -> all 32 banks distinct, conflict-free.
// ---------------------------------------------------------------------------
#define AST 40
#define BST 40

__global__ __launch_bounds__(256, 2) void convkan_mma16(
        const float* __restrict__ bias, float* __restrict__ out) {
    __shared__ __align__(16) __half As[2][128][AST];
    __shared__ __align__(16) __half Bs[2][128][BST];

    const int bid  = blockIdx.x;          // 0..255
    const int n    = bid >> 5;
    const int h0   = (bid & 31) << 1;     // 2 image rows
    const int tid  = threadIdx.x;
    const int warp = tid >> 5;
    const int lane = tid & 31;
    const int gid  = lane >> 2;
    const int tig  = lane & 3;
    const int wm   = (warp & 3) * 32;
    const int wn   = (warp >> 2) * 64;

    // loaders: thread -> (row 0..127, 32B segment 0/1)
    const int lrow = tid >> 1;
    const int lseg = (tid & 1) * 16;      // half offset (32B)
    const int hl   = lrow >> 6;
    const int wl   = lrow & 63;

    float acc[2][8][4];
    #pragma unroll
    for (int mt = 0; mt < 2; mt++)
        #pragma unroll
        for (int nt = 0; nt < 8; nt++)
            #pragma unroll
            for (int q = 0; q < 4; q++) acc[mt][nt][q] = 0.0f;

    uint4 pa[2], pb[2];

    // prefetch K-tile 0 (tap 0 -> kh=0,kw=0, ct=0)
    {
        const __half* ap = g_A + (((size_t)(n*HP + h0 + hl)) * WP + wl) * CEXP + lseg;
        pa[0] = *(const uint4*)ap;
        pa[1] = *(const uint4*)(ap + 8);
        const __half* bp = g_Wt + (size_t)lrow * KTOT + lseg;
        pb[0] = *(const uint4*)bp;
        pb[1] = *(const uint4*)(bp + 8);
    }

    int tap = 0, ct = 0, kh = 0, kw = 0;

    for (int kt = 0; kt < NIT; ++kt) {
        const int buf = kt & 1;
        // store prefetched tile
        {
            __half* as = &As[buf][lrow][lseg];
            *(uint4*)as       = pa[0];
            *(uint4*)(as + 8) = pa[1];
            __half* bs = &Bs[buf][lrow][lseg];
            *(uint4*)bs       = pb[0];
            *(uint4*)(bs + 8) = pb[1];
        }
        __syncthreads();

        // prefetch next tile into registers
        if (kt + 1 < NIT) {
            if (++ct == NCH) { ct = 0; ++tap; if (++kw == 3) { kw = 0; ++kh; } }
            const __half* ap = g_A
                + (((size_t)(n*HP + h0 + hl + kh)) * WP + (wl + kw)) * CEXP
                + ct * BKH + lseg;
            pa[0] = *(const uint4*)ap;
            pa[1] = *(const uint4*)(ap + 8);
            const __half* bp = g_Wt
                + (size_t)lrow * KTOT + tap * CEXP + ct * BKH + lseg;
            pb[0] = *(const uint4*)bp;
            pb[1] = *(const uint4*)(bp + 8);
        }

        // compute: 2 k-steps of m16n8k16
        #pragma unroll
        for (int kk = 0; kk < 2; ++kk) {
            const int kb = kk * 16 + tig * 2;
            uint32_t afr[2][4];
            #pragma unroll
            for (int mt = 0; mt < 2; mt++) {
                int r0 = wm + mt * 16 + gid;
                afr[mt][0] = *(const uint32_t*)&As[buf][r0    ][kb    ];
                afr[mt][1] = *(const uint32_t*)&As[buf][r0 + 8][kb    ];
                afr[mt][2] = *(const uint32_t*)&As[buf][r0    ][kb + 8];
                afr[mt][3] = *(const uint32_t*)&As[buf][r0 + 8][kb + 8];
            }
            #pragma unroll
            for (int nt = 0; nt < 8; nt++) {
                int cn = wn + nt * 8 + gid;
                uint32_t b0 = *(const uint32_t*)&Bs[buf][cn][kb    ];
                uint32_t b1 = *(const uint32_t*)&Bs[buf][cn][kb + 8];
                #pragma unroll
                for (int mt = 0; mt < 2; mt++) {
                    float* d = acc[mt][nt];
                    asm volatile(
                        "mma.sync.aligned.m16n8k16.row.col.f32.f16.f16.f32 "
                        "{%0,%1,%2,%3}, {%4,%5,%6,%7}, {%8,%9}, {%0,%1,%2,%3};\n"
                        : "+f"(d[0]), "+f"(d[1]), "+f"(d[2]), "+f"(d[3])
                        : "r"(afr[mt][0]), "r"(afr[mt][1]),
                          "r"(afr[mt][2]), "r"(afr[mt][3]),
                          "r"(b0), "r"(b1));
                }
            }
        }
        __syncthreads();
    }

    // epilogue: D frag (gid,tig): rows gid,gid+8; cols 2tig,2tig+1
    #pragma unroll
    for (int nt = 0; nt < 8; nt++) {
        int col = wn + nt * 8 + tig * 2;
        float bx = bias[col], by = bias[col + 1];
        #pragma unroll
        for (int mt = 0; mt < 2; mt++) {
            int row0 = bid * 128 + wm + mt * 16 + gid;
            float2 v0 = make_float2(acc[mt][nt][0] + bx, acc[mt][nt][1] + by);
            float2 v1 = make_float2(acc[mt][nt][2] + bx, acc[mt][nt][3] + by);
            *(float2*)(out + (size_t)row0 * COUT + col)       = v0;
            *(float2*)(out + (size_t)(row0 + 8) * COUT + col) = v1;
        }
    }
}

// ---------------------------------------------------------------------------
extern "C" void kernel_launch(void* const* d_in, const int* in_sizes, int n_in,
                              void* d_out, int out_size) {
    const float* x        = (const float*)d_in[0];
    const float* base_w   = (const float*)d_in[1];
    const float* spline_w = (const float*)d_in[2];
    const float* bias     = (const float*)d_in[3];
    float* out = (float*)d_out;

    {
        int total = B_*HP*WP*CIN;
        expand_kernel<<<(total + 255)/256, 256>>>(x);
    }
    {
        int total = COUT*KTOT;
        wpack_kernel<<<(total + 255)/256, 256>>>(base_w, spline_w);
    }
    convkan_mma16<<<256, 256>>>(bias, out);
}

// round 7
// speedup vs baseline: 7.7041x; 1.8116x over previous
#include <cuda_runtime.h>
#include <cuda_fp16.h>
#include <math.h>
#include <stdint.h>

// ---------------------------------------------------------------------------
// ConvKAN as conv3x3-GEMM over expanded features (silu + 6 cubic B-spline
// bases), fp16 inputs, fp32 accumulation.
//   M = 32768 pixels, N = 128 outputs, K = 9*448 = 4032
// GEMM: mma.sync.m16n8k16 + ldmatrix.x4 (SW128 swizzle, conflict-free)
//       + cp.async.cg double-buffered K-tiles of 64.
// ---------------------------------------------------------------------------

#define B_      8
#define H_      64
#define W_      64
#define CIN     64
#define COUT    128
#define FEAT    7
#define CEXP    (CIN*FEAT)   // 448
#define HP      (H_+2)
#define WP      (W_+2)
#define KTOT    (9*CEXP)     // 4032
#define BKH     64           // halves per K-tile (128B rows)
#define NCH     (CEXP/BKH)   // 7 chunks per tap
#define NIT     (9*NCH)      // 63 K-tiles

__device__ __align__(128) __half g_A[(size_t)B_*HP*WP*CEXP];  // expanded (halo=f(0))
__device__ __align__(128) __half g_Wt[(size_t)COUT*KTOT];     // packed weights [o][k]

__device__ __forceinline__ uint32_t smem_u32(const void* p) {
    uint32_t a;
    asm("{ .reg .u64 t; cvta.to.shared.u64 t, %1; cvt.u32.u64 %0, t; }"
        : "=r"(a) : "l"(p));
    return a;
}
#define CP_ASYNC16(dst, src) \
    asm volatile("cp.async.cg.shared.global [%0], [%1], 16;" :: "r"(dst), "l"(src))
#define CP_COMMIT() asm volatile("cp.async.commit_group;" ::: "memory")
#define CP_WAIT(n)  asm volatile("cp.async.wait_group %0;" :: "n"(n) : "memory")
#define LDSM_X4(r, a) \
    asm volatile("ldmatrix.sync.aligned.m8n8.x4.shared.b16 {%0,%1,%2,%3}, [%4];" \
        : "=r"((r)[0]), "=r"((r)[1]), "=r"((r)[2]), "=r"((r)[3]) : "r"(a))

// ---------------------------------------------------------------------------
// Kernel 1: expand x -> A (incl. halo = features(0); bases(0) != 0!)
// Block = 4 pixels x 64 channels; smem staging -> coalesced uint4 output.
// ---------------------------------------------------------------------------
__global__ __launch_bounds__(256) void expand_kernel(const float* __restrict__ x) {
    __shared__ __half st[4*CEXP];
    int t = threadIdx.x;
    int p = t >> 6, c = t & 63;
    int pix = blockIdx.x * 4 + p;
    int wp  = pix % WP;
    int t1  = pix / WP;
    int hp  = t1 % HP;
    int n   = t1 / HP;

    bool halo = (hp == 0 || hp == HP-1 || wp == 0 || wp == WP-1);
    float v = halo ? 0.0f
                   : x[(((size_t)n * H_ + (hp-1)) * W_ + (wp-1)) * CIN + c];

    float s = v / (1.0f + expf(-v));

    float b0=0.f,b1=0.f,b2=0.f,b3=0.f,b4=0.f,b5=0.f;
    float tpos = (v + 3.0f) * 1.5f;
    float fj = floorf(tpos);
    int j = (int)fj;
    if (j >= 0 && j <= 8) {
        float u  = tpos - fj;
        float um = 1.0f - u;
        float u2 = u*u, u3 = u2*u;
        const float k6 = 1.0f/6.0f;
        float n0 = um*um*um*k6;
        float n1 = (3.0f*u3 - 6.0f*u2 + 4.0f)*k6;
        float n2 = (-3.0f*u3 + 3.0f*u2 + 3.0f*u + 1.0f)*k6;
        float n3 = u3*k6;
        int m;
        m = j-3; if (m==0) b0=n0; else if (m==1) b1=n0; else if (m==2) b2=n0; else if (m==3) b3=n0; else if (m==4) b4=n0; else if (m==5) b5=n0;
        m = j-2; if (m==0) b0=n1; else if (m==1) b1=n1; else if (m==2) b2=n1; else if (m==3) b3=n1; else if (m==4) b4=n1; else if (m==5) b5=n1;
        m = j-1; if (m==0) b0=n2; else if (m==1) b1=n2; else if (m==2) b2=n2; else if (m==3) b3=n2; else if (m==4) b4=n2; else if (m==5) b5=n2;
        m = j;   if (m==0) b0=n3; else if (m==1) b1=n3; else if (m==2) b2=n3; else if (m==3) b3=n3; else if (m==4) b4=n3; else if (m==5) b5=n3;
    }
    __half* d = st + p * CEXP + c * FEAT;
    d[0]=__float2half_rn(s);  d[1]=__float2half_rn(b0);
    d[2]=__float2half_rn(b1); d[3]=__float2half_rn(b2);
    d[4]=__float2half_rn(b3); d[5]=__float2half_rn(b4);
    d[6]=__float2half_rn(b5);
    __syncthreads();

    const uint4* s4 = (const uint4*)st;
    uint4* d4 = (uint4*)(g_A + (size_t)blockIdx.x * 4 * CEXP);
    if (t < 224) d4[t] = s4[t];   // 4*448 halves = 224 uint4
}

// ---------------------------------------------------------------------------
// Kernel 2: pack weights -> g_Wt[o][k], k = tap*448 + c*7 + t, i = c*9 + tap
// ---------------------------------------------------------------------------
__global__ void wpack_kernel(const float* __restrict__ base_w,
                             const float* __restrict__ spline_w) {
    int idx = blockIdx.x * blockDim.x + threadIdx.x;
    if (idx >= COUT*KTOT) return;
    int o = idx / KTOT;
    int k = idx - o * KTOT;
    int tap = k / CEXP;
    int cc  = k - tap * CEXP;
    int c   = cc / FEAT;
    int t   = cc - c * FEAT;
    int i   = c * 9 + tap;
    float w = (t == 0) ? base_w[(size_t)o * 576 + i]
                       : spline_w[((size_t)o * 576 + i) * 6 + (t - 1)];
    g_Wt[idx] = __float2half_rn(w);
}

// ---------------------------------------------------------------------------
// Kernel 3: fp16 HMMA GEMM, BM=128 x BN=128 x BK=64 halves.
// smem (dynamic 64KB): A bufs @0,@16K; B bufs @32K,@48K. 128B rows, SW128
// swizzle (16B unit f of row r: f ^= r&7) -> ldmatrix conflict-free.
// 8 warps = 4(m) x 2(n); warp 32x64; per k16-step: 2 A-ldsm.x4, 4 B-ldsm.x4,
// 16 mma.m16n8k16.
// ---------------------------------------------------------------------------
#define ABUF(b)  ((b)*16384)
#define BBUF(b)  (32768 + (b)*16384)
#define SMEM_TOTAL 65536

__global__ __launch_bounds__(256, 2) void convkan_hmma(
        const float* __restrict__ bias, float* __restrict__ out) {
    extern __shared__ char smem[];
    const uint32_t sb = smem_u32(smem);

    const int bid  = blockIdx.x;          // 0..255
    const int n    = bid >> 5;
    const int h0   = (bid & 31) << 1;     // 2 image rows
    const int tid  = threadIdx.x;
    const int warp = tid >> 5;
    const int lane = tid & 31;
    const int gid  = lane >> 2;
    const int tig  = lane & 3;
    const int wm   = (warp & 3) * 32;
    const int wn   = (warp >> 2) * 64;

    // ---- loader constants: 4 16B units per thread (A and B share row/f) ----
    const __half* aGp[4];
    const __half* bGp[4];
    uint32_t ldst[4];
    #pragma unroll
    for (int i = 0; i < 4; i++) {
        int unit = i * 256 + tid;         // 0..1023
        int row  = unit >> 3;             // 0..127
        int f    = unit & 7;              // 16B unit in 128B row
        int hl   = row >> 6, wl = row & 63;
        aGp[i] = g_A + (((size_t)(n*HP + h0 + hl)) * WP + wl) * CEXP + f * 8;
        bGp[i] = g_Wt + (size_t)row * KTOT + f * 8;
        ldst[i] = sb + row * 128 + (((uint32_t)f ^ (row & 7)) << 4);
    }

    // ---- ldmatrix lane constants ----
    const int rA   = (lane & 7) + ((lane >> 3) & 1) * 8;
    const int segA = lane >> 4;
    const uint32_t aRow = (uint32_t)(wm + rA) * 128;
    const uint32_t aXor = (uint32_t)(rA & 7) << 4;
    const int rB   = (lane & 7) + (((lane >> 4) & 1) ? 8 : 0);
    const int segB = (lane >> 3) & 1;
    const uint32_t bXor = (uint32_t)(rB & 7) << 4;

    float acc[2][8][4];
    #pragma unroll
    for (int mt = 0; mt < 2; mt++)
        #pragma unroll
        for (int nt = 0; nt < 8; nt++)
            #pragma unroll
            for (int q = 0; q < 4; q++) acc[mt][nt][q] = 0.0f;

    // ---- prologue: issue tile 0 (tap0 -> kh=0,kw=0, ct=0) into buf 0 ----
    #pragma unroll
    for (int i = 0; i < 4; i++) {
        CP_ASYNC16(ldst[i] + ABUF(0), aGp[i]);
        CP_ASYNC16(ldst[i] + BBUF(0), bGp[i]);
    }
    CP_COMMIT();

    int tap = 0, ct = 0, kh = 0, kw = 0;

    for (int kt = 0; kt < NIT; ++kt) {
        const int buf = kt & 1;

        if (kt + 1 < NIT) {
            if (++ct == NCH) { ct = 0; ++tap; if (++kw == 3) { kw = 0; ++kh; } }
            const int koffA = (kh * WP + kw) * CEXP + ct * BKH;
            const int koffB = tap * CEXP + ct * BKH;
            const int nb = buf ^ 1;
            #pragma unroll
            for (int i = 0; i < 4; i++) {
                CP_ASYNC16(ldst[i] + ABUF(nb), aGp[i] + koffA);
                CP_ASYNC16(ldst[i] + BBUF(nb), bGp[i] + koffB);
            }
            CP_COMMIT();
            CP_WAIT(1);
        } else {
            CP_WAIT(0);
        }
        __syncthreads();

        const uint32_t Ab = sb + ABUF(buf);
        const uint32_t Bb = sb + BBUF(buf);

        #pragma unroll
        for (int kk = 0; kk < 4; ++kk) {
            uint32_t afr[2][4];
            #pragma unroll
            for (int mt = 0; mt < 2; mt++) {
                uint32_t addr = Ab + aRow + mt * 2048
                              + (((uint32_t)(kk * 32 + segA * 16)) ^ aXor);
                LDSM_X4(afr[mt], addr);
            }
            uint32_t bfr[4][4];
            #pragma unroll
            for (int np = 0; np < 4; np++) {
                uint32_t addr = Bb + (uint32_t)(wn + np * 16 + rB) * 128
                              + (((uint32_t)(kk * 32 + segB * 16)) ^ bXor);
                LDSM_X4(bfr[np], addr);
            }
            #pragma unroll
            for (int np = 0; np < 4; np++)
                #pragma unroll
                for (int u = 0; u < 2; u++) {
                    const uint32_t bb0 = bfr[np][u * 2];
                    const uint32_t bb1 = bfr[np][u * 2 + 1];
                    #pragma unroll
                    for (int mt = 0; mt < 2; mt++) {
                        float* d = acc[mt][np * 2 + u];
                        asm volatile(
                            "mma.sync.aligned.m16n8k16.row.col.f32.f16.f16.f32 "
                            "{%0,%1,%2,%3}, {%4,%5,%6,%7}, {%8,%9}, {%0,%1,%2,%3};\n"
                            : "+f"(d[0]), "+f"(d[1]), "+f"(d[2]), "+f"(d[3])
                            : "r"(afr[mt][0]), "r"(afr[mt][1]),
                              "r"(afr[mt][2]), "r"(afr[mt][3]),
                              "r"(bb0), "r"(bb1));
                    }
                }
        }
        __syncthreads();
    }

    // ---- epilogue: D frag (gid,tig): rows gid,gid+8; cols 2tig,2tig+1 ----
    #pragma unroll
    for (int nt = 0; nt < 8; nt++) {
        int col = wn + nt * 8 + tig * 2;
        float bx = bias[col], by = bias[col + 1];
        #pragma unroll
        for (int mt = 0; mt < 2; mt++) {
            int row0 = bid * 128 + wm + mt * 16 + gid;
            float2 v0 = make_float2(acc[mt][nt][0] + bx, acc[mt][nt][1] + by);
            float2 v1 = make_float2(acc[mt][nt][2] + bx, acc[mt][nt][3] + by);
            *(float2*)(out + (size_t)row0 * COUT + col)       = v0;
            *(float2*)(out + (size_t)(row0 + 8) * COUT + col) = v1;
        }
    }
}

// ---------------------------------------------------------------------------
extern "C" void kernel_launch(void* const* d_in, const int* in_sizes, int n_in,
                              void* d_out, int out_size) {
    const float* x        = (const float*)d_in[0];
    const float* base_w   = (const float*)d_in[1];
    const float* spline_w = (const float*)d_in[2];
    const float* bias     = (const float*)d_in[3];
    float* out = (float*)d_out;

    expand_kernel<<<(B_*HP*WP)/4, 256>>>(x);
    {
        int total = COUT*KTOT;
        wpack_kernel<<<(total + 255)/256, 256>>>(base_w, spline_w);
    }
    cudaFuncSetAttribute(convkan_hmma,
                         cudaFuncAttributeMaxDynamicSharedMemorySize, SMEM_TOTAL);
    convkan_hmma<<<256, 256, SMEM_TOTAL>>>(bias, out);
}

// round 10
// speedup vs baseline: 8.3056x; 1.0781x over previous
#include <cuda_runtime.h>
#include <cuda_fp16.h>
#include <math.h>
#include <stdint.h>

// ---------------------------------------------------------------------------
// ConvKAN as conv3x3-GEMM over expanded features (silu + 6 cubic B-spline
// bases), fp16 inputs, fp32 accumulation.
//   M = 32768 pixels, N = 128 outputs, K = 9*448 = 4032
// GEMM: mma.sync.m16n8k16 + ldmatrix.x4 (SW128 swizzle) + cp.async.cg,
//       3-stage pipeline (prefetch distance 2), 2 barriers per K-tile
//       (barrier A: stage reuse safety; barrier B: cross-thread cp.async
//        visibility -- wait_group only covers the calling thread's groups!)
// ---------------------------------------------------------------------------

#define B_      8
#define H_      64
#define W_      64
#define CIN     64
#define COUT    128
#define FEAT    7
#define CEXP    (CIN*FEAT)   // 448
#define HP      (H_+2)
#define WP      (W_+2)
#define KTOT    (9*CEXP)     // 4032
#define BKH     64           // halves per K-tile (128B rows)
#define NCH     (CEXP/BKH)   // 7 chunks per tap
#define NIT     (9*NCH)      // 63 K-tiles

__device__ __align__(128) __half g_A[(size_t)B_*HP*WP*CEXP];  // expanded (halo=f(0))
__device__ __align__(128) __half g_Wt[(size_t)COUT*KTOT];     // packed weights [o][k]

__device__ __forceinline__ uint32_t smem_u32(const void* p) {
    uint32_t a;
    asm("{ .reg .u64 t; cvta.to.shared.u64 t, %1; cvt.u32.u64 %0, t; }"
        : "=r"(a) : "l"(p));
    return a;
}
#define CP_ASYNC16(dst, src) \
    asm volatile("cp.async.cg.shared.global [%0], [%1], 16;" :: "r"(dst), "l"(src))
#define CP_COMMIT() asm volatile("cp.async.commit_group;" ::: "memory")
#define CP_WAIT(n)  asm volatile("cp.async.wait_group %0;" :: "n"(n) : "memory")
#define LDSM_X4(r, a) \
    asm volatile("ldmatrix.sync.aligned.m8n8.x4.shared.b16 {%0,%1,%2,%3}, [%4];" \
        : "=r"((r)[0]), "=r"((r)[1]), "=r"((r)[2]), "=r"((r)[3]) : "r"(a))

// ---------------------------------------------------------------------------
// Kernel 1 (fused): blocks [0, NEXP) expand x -> A; blocks [NEXP, ...) pack W.
// expand: 4 pixels x 64 channels per block, smem staging, coalesced output.
// halo pixels get features(0) (bases(0) != 0!).
// ---------------------------------------------------------------------------
#define NEXP  ((B_*HP*WP)/4)                 // 8712 expand blocks
#define NWPK  ((COUT*KTOT + 255)/256)        // 2016 wpack blocks

__global__ __launch_bounds__(256) void prep_kernel(
        const float* __restrict__ x,
        const float* __restrict__ base_w,
        const float* __restrict__ spline_w) {
    if (blockIdx.x >= NEXP) {
        // ---- weight pack: g_Wt[o][k], k = tap*448 + c*7 + t, i = c*9 + tap
        int idx = (blockIdx.x - NEXP) * 256 + threadIdx.x;
        if (idx >= COUT*KTOT) return;
        int o = idx / KTOT;
        int k = idx - o * KTOT;
        int tap = k / CEXP;
        int cc  = k - tap * CEXP;
        int c   = cc / FEAT;
        int t   = cc - c * FEAT;
        int i   = c * 9 + tap;
        float w = (t == 0) ? base_w[(size_t)o * 576 + i]
                           : spline_w[((size_t)o * 576 + i) * 6 + (t - 1)];
        g_Wt[idx] = __float2half_rn(w);
        return;
    }

    __shared__ __half st[4*CEXP];
    int t = threadIdx.x;
    int p = t >> 6, c = t & 63;
    int pix = blockIdx.x * 4 + p;
    int wp  = pix % WP;
    int t1  = pix / WP;
    int hp  = t1 % HP;
    int n   = t1 / HP;

    bool halo = (hp == 0 || hp == HP-1 || wp == 0 || wp == WP-1);
    float v = halo ? 0.0f
                   : x[(((size_t)n * H_ + (hp-1)) * W_ + (wp-1)) * CIN + c];

    float s = v / (1.0f + __expf(-v));

    __half* d = st + p * CEXP + c * FEAT;
    d[0] = __float2half_rn(s);
    d[1] = __half(0.0f); d[2] = __half(0.0f); d[3] = __half(0.0f);
    d[4] = __half(0.0f); d[5] = __half(0.0f); d[6] = __half(0.0f);

    // uniform cubic B-spline: interval j = floor((v+3)*1.5) in [0,8],
    // pieces n0..n3 land in basis slots m = j-3..j, clipped to [0,5].
    float tpos = (v + 3.0f) * 1.5f;
    float fj = floorf(tpos);
    int j = (int)fj;
    if (j >= 0 && j <= 8) {
        float u  = tpos - fj;
        float um = 1.0f - u;
        float u2 = u*u, u3 = u2*u;
        const float k6 = 1.0f/6.0f;
        float n0 = um*um*um*k6;
        float n1 = (3.0f*u3 - 6.0f*u2 + 4.0f)*k6;
        float n2 = (-3.0f*u3 + 3.0f*u2 + 3.0f*u + 1.0f)*k6;
        float n3 = u3*k6;
        int m0 = j - 3;
        if (m0     >= 0 && m0     < 6) d[1 + m0]     = __float2half_rn(n0);
        if (m0 + 1 >= 0 && m0 + 1 < 6) d[2 + m0]     = __float2half_rn(n1);
        if (m0 + 2 >= 0 && m0 + 2 < 6) d[3 + m0]     = __float2half_rn(n2);
        if (m0 + 3 >= 0 && m0 + 3 < 6) d[4 + m0]     = __float2half_rn(n3);
    }
    __syncthreads();

    const uint4* s4 = (const uint4*)st;
    uint4* d4 = (uint4*)(g_A + (size_t)blockIdx.x * 4 * CEXP);
    if (t < 224) d4[t] = s4[t];   // 4*448 halves = 224 uint4
}

// ---------------------------------------------------------------------------
// Kernel 2: fp16 HMMA GEMM, BM=128 x BN=128 x BK=64 halves.
// 3-stage smem pipeline: stage s at s*32KB (A @+0 16KB, B @+16KB).
// 128B rows, SW128 swizzle (16B unit f of row r: f ^= r&7) -> ldmatrix
// conflict-free. 8 warps = 4(m) x 2(n); warp 32x64.
// ---------------------------------------------------------------------------
#define STG(s)   ((s)*32768)
#define SMEM_TOTAL (3*32768)   // 96 KB

__global__ __launch_bounds__(256, 2) void convkan_hmma(
        const float* __restrict__ bias, float* __restrict__ out) {
    extern __shared__ char smem[];
    const uint32_t sb = smem_u32(smem);

    const int bid  = blockIdx.x;          // 0..255
    const int n    = bid >> 5;
    const int h0   = (bid & 31) << 1;     // 2 image rows
    const int tid  = threadIdx.x;
    const int warp = tid >> 5;
    const int lane = tid & 31;
    const int gid  = lane >> 2;
    const int tig  = lane & 3;
    const int wm   = (warp & 3) * 32;
    const int wn   = (warp >> 2) * 64;

    // ---- loader constants: 4 16B units per thread (A and B share row/f) ----
    const __half* aGp[4];
    const __half* bGp[4];
    uint32_t ldst[4];
    #pragma unroll
    for (int i = 0; i < 4; i++) {
        int unit = i * 256 + tid;         // 0..1023
        int row  = unit >> 3;             // 0..127
        int f    = unit & 7;              // 16B unit in 128B row
        int hl   = row >> 6, wl = row & 63;
        aGp[i] = g_A + (((size_t)(n*HP + h0 + hl)) * WP + wl) * CEXP + f * 8;
        bGp[i] = g_Wt + (size_t)row * KTOT + f * 8;
        ldst[i] = sb + row * 128 + (((uint32_t)f ^ (row & 7)) << 4);
    }

    // ---- ldmatrix lane constants ----
    const int rA   = (lane & 7) + ((lane >> 3) & 1) * 8;
    const int segA = lane >> 4;
    const uint32_t aRow = (uint32_t)(wm + rA) * 128;
    const uint32_t aXor = (uint32_t)(rA & 7) << 4;
    const int rB   = (lane & 7) + (((lane >> 4) & 1) ? 8 : 0);
    const int segB = (lane >> 3) & 1;
    const uint32_t bXor = (uint32_t)(rB & 7) << 4;

    float acc[2][8][4];
    #pragma unroll
    for (int mt = 0; mt < 2; mt++)
        #pragma unroll
        for (int nt = 0; nt < 8; nt++)
            #pragma unroll
            for (int q = 0; q < 4; q++) acc[mt][nt][q] = 0.0f;

    // ---- prologue: issue tiles 0 and 1 into stages 0, 1 ----
    #pragma unroll
    for (int i = 0; i < 4; i++) {                 // tile 0: tap0,ct0
        CP_ASYNC16(ldst[i] + STG(0), aGp[i]);
        CP_ASYNC16(ldst[i] + STG(0) + 16384, bGp[i]);
    }
    CP_COMMIT();
    #pragma unroll
    for (int i = 0; i < 4; i++) {                 // tile 1: tap0,ct1
        CP_ASYNC16(ldst[i] + STG(1), aGp[i] + BKH);
        CP_ASYNC16(ldst[i] + STG(1) + 16384, bGp[i] + BKH);
    }
    CP_COMMIT();

    // counters at tile 1's state; incremented at loop top -> tile kt+2
    int tap = 0, ct = 1, kh = 0, kw = 0;
    int stage = 0;

    for (int kt = 0; kt < NIT; ++kt) {
        // barrier A: all threads finished computing tile kt-1, so the stage
        // being overwritten below ((kt+2)%3, last held tile kt-1) is free.
        __syncthreads();

        if (kt + 2 < NIT) {
            if (++ct == NCH) { ct = 0; ++tap; if (++kw == 3) { kw = 0; ++kh; } }
            const int koffA = (kh * WP + kw) * CEXP + ct * BKH;
            const int koffB = tap * CEXP + ct * BKH;
            const int ns = STG((stage + 2) % 3);
            #pragma unroll
            for (int i = 0; i < 4; i++) {
                CP_ASYNC16(ldst[i] + ns, aGp[i] + koffA);
                CP_ASYNC16(ldst[i] + ns + 16384, bGp[i] + koffB);
            }
        }
        CP_COMMIT();       // one group per iteration (possibly empty)
        CP_WAIT(2);        // own groups for tile kt complete

        // barrier B: every thread has passed its wait -> ALL threads' tile-kt
        // cp.async data is visible to the whole CTA.
        __syncthreads();

        const uint32_t Ab = sb + STG(stage);
        const uint32_t Bb = Ab + 16384;

        #pragma unroll
        for (int kk = 0; kk < 4; ++kk) {
            uint32_t afr[2][4];
            #pragma unroll
            for (int mt = 0; mt < 2; mt++) {
                uint32_t addr = Ab + aRow + mt * 2048
                              + (((uint32_t)(kk * 32 + segA * 16)) ^ aXor);
                LDSM_X4(afr[mt], addr);
            }
            uint32_t bfr[4][4];
            #pragma unroll
            for (int np = 0; np < 4; np++) {
                uint32_t addr = Bb + (uint32_t)(wn + np * 16 + rB) * 128
                              + (((uint32_t)(kk * 32 + segB * 16)) ^ bXor);
                LDSM_X4(bfr[np], addr);
            }
            #pragma unroll
            for (int np = 0; np < 4; np++)
                #pragma unroll
                for (int u = 0; u < 2; u++) {
                    const uint32_t bb0 = bfr[np][u * 2];
                    const uint32_t bb1 = bfr[np][u * 2 + 1];
                    #pragma unroll
                    for (int mt = 0; mt < 2; mt++) {
                        float* d = acc[mt][np * 2 + u];
                        asm volatile(
                            "mma.sync.aligned.m16n8k16.row.col.f32.f16.f16.f32 "
                            "{%0,%1,%2,%3}, {%4,%5,%6,%7}, {%8,%9}, {%0,%1,%2,%3};\n"
                            : "+f"(d[0]), "+f"(d[1]), "+f"(d[2]), "+f"(d[3])
                            : "r"(afr[mt][0]), "r"(afr[mt][1]),
                              "r"(afr[mt][2]), "r"(afr[mt][3]),
                              "r"(bb0), "r"(bb1));
                    }
                }
        }
        stage = (stage + 1) % 3;
    }

    // ---- epilogue: D frag (gid,tig): rows gid,gid+8; cols 2tig,2tig+1 ----
    #pragma unroll
    for (int nt = 0; nt < 8; nt++) {
        int col = wn + nt * 8 + tig * 2;
        float bx = bias[col], by = bias[col + 1];
        #pragma unroll
        for (int mt = 0; mt < 2; mt++) {
            int row0 = bid * 128 + wm + mt * 16 + gid;
            float2 v0 = make_float2(acc[mt][nt][0] + bx, acc[mt][nt][1] + by);
            float2 v1 = make_float2(acc[mt][nt][2] + bx, acc[mt][nt][3] + by);
            *(float2*)(out + (size_t)row0 * COUT + col)       = v0;
            *(float2*)(out + (size_t)(row0 + 8) * COUT + col) = v1;
        }
    }
}

// ---------------------------------------------------------------------------
extern "C" void kernel_launch(void* const* d_in, const int* in_sizes, int n_in,
                              void* d_out, int out_size) {
    const float* x        = (const float*)d_in[0];
    const float* base_w   = (const float*)d_in[1];
    const float* spline_w = (const float*)d_in[2];
    const float* bias     = (const float*)d_in[3];
    float* out = (float*)d_out;

    prep_kernel<<<NEXP + NWPK, 256>>>(x, base_w, spline_w);
    cudaFuncSetAttribute(convkan_hmma,
                         cudaFuncAttributeMaxDynamicSharedMemorySize, SMEM_TOTAL);
    convkan_hmma<<<256, 256, SMEM_TOTAL>>>(bias, out);
}